// round 8
// baseline (speedup 1.0000x reference)
#include <cuda_runtime.h>
#include <cuda_bf16.h>
#include <cstdint>

// Problem shape (fixed by the dataset)
#define B_ 8
#define T_ 4096
#define F_ 512
#define ROWS_ (B_ * T_)

#define GRID_ 148          // 1 CTA per SM; all co-resident
#define BLK_  1024
#define NGRP  4
#define GRP_ROWS (ROWS_ / NGRP)    // 8192 rows = 2 batches per group

// Scratch (no allocations allowed) — device globals.
__device__ float g_z[ROWS_];
__device__ int   g_pos[ROWS_];
__device__ int   g_hlens[B_];
__device__ volatile unsigned g_scan_done[B_];
__device__ unsigned g_bar_count = 0;
__device__ unsigned g_bar_gen   = 0;

// Software grid barrier (all 148 CTAs co-resident at 1 CTA/SM).
__device__ __forceinline__ void grid_barrier() {
    __syncthreads();
    if (threadIdx.x == 0) {
        unsigned gen = *(volatile unsigned*)&g_bar_gen;
        __threadfence();
        unsigned arr = atomicAdd(&g_bar_count, 1u);
        if (arr == GRID_ - 1) {
            atomicExch(&g_bar_count, 0u);
            __threadfence();
            atomicAdd(&g_bar_gen, 1u);
        } else {
            while (*(volatile unsigned*)&g_bar_gen == gen) { }
        }
        __threadfence();
    }
    __syncthreads();
}

__global__ void __launch_bounds__(BLK_, 1)
k_fused(const float* __restrict__ feat, const float* __restrict__ W,
        float* __restrict__ out, int out_size) {
    const int tid  = threadIdx.x;
    const int lane = tid & 31;
    const int wid  = tid >> 5;                 // 0..31
    const int bid  = blockIdx.x;

    __shared__ int warp_sums[32];
    __shared__ int warp_incl[32];

    // W in registers (16 floats per lane).
    const float4* w4 = reinterpret_cast<const float4*>(W);
    float4 wreg[4];
#pragma unroll
    for (int i = 0; i < 4; i++) wreg[i] = w4[lane + i * 32];

    // Epoch pipeline: e in [0, NGRP].
    //   e < NGRP : GEMV group e (CTAs 2..147)
    //   e >= 1   : CTAs 0,1 scan batch 2*(e-1)+bid; then ALL compact group e-1
    for (int e = 0; e <= NGRP; e++) {

        // ---------------- scanners: scan group e-1 (z ready via barrier) ----
        if (e >= 1 && bid < 2) {
            const int b = 2 * (e - 1) + bid;
            const float* zb = g_z + b * T_;
            const int t0 = tid * 4;            // 1024 threads * 4 = 4096

            int flags[4];
            int cnt = 0;
#pragma unroll
            for (int k = 0; k < 4; k++) {
                int t = t0 + k;
                float c = zb[t];
                float l = (t > 0)      ? zb[t - 1] : c;
                float r = (t < T_ - 1) ? zb[t + 1] : c;
                flags[k] = (c >= l) & (c >= r);
                cnt += flags[k];
            }
            int v = cnt;
#pragma unroll
            for (int o = 1; o < 32; o <<= 1) {
                int n = __shfl_up_sync(0xFFFFFFFFu, v, o);
                if (lane >= o) v += n;
            }
            if (lane == 31) warp_sums[wid] = v;
            __syncthreads();
            if (wid == 0) {
                int s = warp_sums[lane];
#pragma unroll
                for (int o = 1; o < 32; o <<= 1) {
                    int n = __shfl_up_sync(0xFFFFFFFFu, s, o);
                    if (lane >= o) s += n;
                }
                warp_incl[lane] = s;
            }
            __syncthreads();

            int excl = (v - cnt) + (wid > 0 ? warp_incl[wid - 1] : 0);
#pragma unroll
            for (int k = 0; k < 4; k++) {
                int t = t0 + k;
                g_pos[b * T_ + t] = flags[k] ? excl : -1;
                excl += flags[k];
            }
            if (tid == 0) {
                int hl = warp_incl[31];
                g_hlens[b] = hl;
                if (out_size >= ROWS_ * F_ + B_)
                    out[(size_t)ROWS_ * F_ + b] = (float)hl;
            }
            __syncthreads();
            if (tid == 0) {
                __threadfence();               // publish pos/hlens
                g_scan_done[b] = 1u;
            }
        }

        // ---------------- GEMV group e (reads) — CTAs 2..147 ---------------
        if (e < NGRP && bid >= 2) {
            // 146 CTAs * 32 warps = 4672 warps; warps gw<4096 take 2 rows.
            const int gw = (bid - 2) * 32 + wid;
            const int r0 = e * GRP_ROWS + gw * 2;
            if (gw < GRP_ROWS / 2) {
                const float4* f0 = reinterpret_cast<const float4*>(feat + (size_t)(r0 + 0) * F_);
                const float4* f1 = reinterpret_cast<const float4*>(feat + (size_t)(r0 + 1) * F_);
                float s0 = 0.f, s1 = 0.f;
#pragma unroll
                for (int i = 0; i < 4; i++) {
                    const int idx = lane + i * 32;
                    const float4 w = wreg[i];
                    float4 a0 = f0[idx];
                    float4 a1 = f1[idx];
                    s0 += a0.x * w.x + a0.y * w.y + a0.z * w.z + a0.w * w.w;
                    s1 += a1.x * w.x + a1.y * w.y + a1.z * w.z + a1.w * w.w;
                }
#pragma unroll
                for (int o = 16; o > 0; o >>= 1) {
                    s0 += __shfl_down_sync(0xFFFFFFFFu, s0, o);
                    s1 += __shfl_down_sync(0xFFFFFFFFu, s1, o);
                }
                if (lane == 0) {
                    g_z[r0 + 0] = s0;
                    g_z[r0 + 1] = s1;
                }
            }
        }

        // ---------------- compact group e-1 (writes) — ALL CTAs ------------
        if (e >= 1) {
            const int b0 = 2 * (e - 1);
            if (tid == 0) {
                while (g_scan_done[b0] == 0u)     __nanosleep(100);
                while (g_scan_done[b0 + 1] == 0u) __nanosleep(100);
                __threadfence();               // acquire pos/hlens
            }
            __syncthreads();

            const int hl0 = g_hlens[b0];
            const int hl1 = g_hlens[b0 + 1];

            const int sub = tid >> 7;          // 0..7 (8 groups of 128 threads)
            const int j   = tid & 127;         // float4 index within row
            const float4 z4 = make_float4(0.f, 0.f, 0.f, 0.f);
            const int gbeg = (e - 1) * GRP_ROWS;
            const int gend = e * GRP_ROWS;

            for (int row = gbeg + bid * 8 + sub; row < gend; row += GRID_ * 8) {
                const int b = row >> 12;       // T_ = 4096
                const int t = row & (T_ - 1);
                const int p  = g_pos[row];
                const int hl = (b == b0) ? hl0 : hl1;

                if (p >= 0) {
                    const float4* s = reinterpret_cast<const float4*>(feat + (size_t)row * F_);
                    float4* d = reinterpret_cast<float4*>(out + ((size_t)b * T_ + p) * F_);
                    __stcs(&d[j], s[j]);
                }
                if (t >= hl) {
                    float4* d = reinterpret_cast<float4*>(out + (size_t)row * F_);
                    __stcs(&d[j], z4);
                }
            }
        }

        grid_barrier();                        // z(group e) ready for epoch e+1
    }

    // Reset scan flags for the next graph replay (everyone is past all reads).
    if (bid == 0 && tid < B_) g_scan_done[tid] = 0u;
}

extern "C" void kernel_launch(void* const* d_in, const int* in_sizes, int n_in,
                              void* d_out, int out_size) {
    const float* feat = (const float*)d_in[0];
    const float* W    = (const float*)d_in[1];
    float* out        = (float*)d_out;
    k_fused<<<GRID_, BLK_>>>(feat, W, out, out_size);
}

// round 9
// speedup vs baseline: 1.5990x; 1.5990x over previous
#include <cuda_runtime.h>
#include <cuda_bf16.h>
#include <cstdint>

// Problem shape (fixed by the dataset)
#define B_ 8
#define T_ 4096
#define F_ 512
#define ROWS_ (B_ * T_)

#define GRID_ 148          // 1 CTA per SM; all co-resident
#define BLK_  1024

// Scratch (no allocations allowed) — device globals.
__device__ float g_z[ROWS_];       // linear scores (monotone-equiv. for peaks)
__device__ int   g_pos[ROWS_];     // compaction destination per row, -1 if not peak
__device__ int   g_hlens[B_];      // peak counts per batch
__device__ unsigned g_bar_count = 0;
__device__ unsigned g_bar_gen   = 0;

// Software grid barrier (all 148 CTAs co-resident at 1 CTA/SM).
__device__ __forceinline__ void grid_barrier() {
    __syncthreads();
    if (threadIdx.x == 0) {
        unsigned gen = *(volatile unsigned*)&g_bar_gen;
        __threadfence();                       // publish this block's phase writes
        unsigned arr = atomicAdd(&g_bar_count, 1u);
        if (arr == GRID_ - 1) {
            atomicExch(&g_bar_count, 0u);
            __threadfence();
            atomicAdd(&g_bar_gen, 1u);         // release
        } else {
            while (*(volatile unsigned*)&g_bar_gen == gen) { }
        }
        __threadfence();                       // acquire other blocks' writes
    }
    __syncthreads();
}

__global__ void __launch_bounds__(BLK_, 1)
k_fused(const float* __restrict__ feat, const float* __restrict__ W,
        float* __restrict__ out, int out_size) {
    const int tid  = threadIdx.x;
    const int lane = tid & 31;
    const int wid  = tid >> 5;                 // 0..31
    const int bid  = blockIdx.x;

    __shared__ int warp_sums[32];
    __shared__ int warp_incl[32];

    // ------------------------------------------------------------------
    // Phase 1: GEMV (reads) + unconditional zero-fill of out (writes),
    // interleaved in one stream so both DRAM directions are busy.
    // FOUR rows per warp per iteration: 16 independent LDG.128 in flight,
    // 16 fire-and-forget STG.128 zeros, 4 independent reduce chains.
    {
        const float4* w4 = reinterpret_cast<const float4*>(W);
        float4 wreg[4];
#pragma unroll
        for (int i = 0; i < 4; i++) wreg[i] = w4[lane + i * 32];
        const float4 z4 = make_float4(0.f, 0.f, 0.f, 0.f);

        for (int row0 = bid * 128 + wid * 4; row0 < ROWS_; row0 += GRID_ * 128) {
            const float4* f0 = reinterpret_cast<const float4*>(feat + (size_t)(row0 + 0) * F_);
            const float4* f1 = reinterpret_cast<const float4*>(feat + (size_t)(row0 + 1) * F_);
            const float4* f2 = reinterpret_cast<const float4*>(feat + (size_t)(row0 + 2) * F_);
            const float4* f3 = reinterpret_cast<const float4*>(feat + (size_t)(row0 + 3) * F_);

            // All 16 loads issued up front.
            float4 a[4][4];
#pragma unroll
            for (int i = 0; i < 4; i++) {
                const int idx = lane + i * 32;
                a[0][i] = f0[idx];
                a[1][i] = f1[idx];
                a[2][i] = f2[idx];
                a[3][i] = f3[idx];
            }

            // Zero-fill the same 4 output rows while loads are in flight.
#pragma unroll
            for (int r = 0; r < 4; r++) {
                float4* d = reinterpret_cast<float4*>(out + (size_t)(row0 + r) * F_);
#pragma unroll
                for (int i = 0; i < 4; i++)
                    __stcs(&d[lane + i * 32], z4);
            }

            float s0 = 0.f, s1 = 0.f, s2 = 0.f, s3 = 0.f;
#pragma unroll
            for (int i = 0; i < 4; i++) {
                const float4 w = wreg[i];
                s0 += a[0][i].x * w.x + a[0][i].y * w.y + a[0][i].z * w.z + a[0][i].w * w.w;
                s1 += a[1][i].x * w.x + a[1][i].y * w.y + a[1][i].z * w.z + a[1][i].w * w.w;
                s2 += a[2][i].x * w.x + a[2][i].y * w.y + a[2][i].z * w.z + a[2][i].w * w.w;
                s3 += a[3][i].x * w.x + a[3][i].y * w.y + a[3][i].z * w.z + a[3][i].w * w.w;
            }
#pragma unroll
            for (int o = 16; o > 0; o >>= 1) {
                s0 += __shfl_down_sync(0xFFFFFFFFu, s0, o);
                s1 += __shfl_down_sync(0xFFFFFFFFu, s1, o);
                s2 += __shfl_down_sync(0xFFFFFFFFu, s2, o);
                s3 += __shfl_down_sync(0xFFFFFFFFu, s3, o);
            }
            if (lane == 0) {
                g_z[row0 + 0] = s0;
                g_z[row0 + 1] = s1;
                g_z[row0 + 2] = s2;
                g_z[row0 + 3] = s3;
            }
        }
    }

    grid_barrier();

    // ------------------------------------------------------------------
    // Phase 2: blocks 0..7 — peak detect + stable exclusive scan per batch.
    if (bid < B_) {
        const int b = bid;
        const float* zb = g_z + b * T_;
        const int t0 = tid * 4;                // 1024 threads * 4 = 4096

        int flags[4];
        int cnt = 0;
#pragma unroll
        for (int k = 0; k < 4; k++) {
            int t = t0 + k;
            float c = zb[t];
            float l = (t > 0)      ? zb[t - 1] : c;
            float r = (t < T_ - 1) ? zb[t + 1] : c;
            flags[k] = (c >= l) & (c >= r);
            cnt += flags[k];
        }

        int v = cnt;
#pragma unroll
        for (int o = 1; o < 32; o <<= 1) {
            int n = __shfl_up_sync(0xFFFFFFFFu, v, o);
            if (lane >= o) v += n;
        }
        if (lane == 31) warp_sums[wid] = v;
        __syncthreads();
        if (wid == 0) {
            int s = warp_sums[lane];
#pragma unroll
            for (int o = 1; o < 32; o <<= 1) {
                int n = __shfl_up_sync(0xFFFFFFFFu, s, o);
                if (lane >= o) s += n;
            }
            warp_incl[lane] = s;
        }
        __syncthreads();

        int excl = (v - cnt) + (wid > 0 ? warp_incl[wid - 1] : 0);
#pragma unroll
        for (int k = 0; k < 4; k++) {
            int t = t0 + k;
            g_pos[b * T_ + t] = flags[k] ? excl : -1;
            excl += flags[k];
        }
        if (tid == 0) {
            int hl = warp_incl[31];
            g_hlens[b] = hl;
            if (out_size >= ROWS_ * F_ + B_)
                out[(size_t)ROWS_ * F_ + b] = (float)hl;
        }
    }

    grid_barrier();

    // ------------------------------------------------------------------
    // Phase 3: copy PEAK rows only (tail already zeroed in phase 1).
    // 1024 threads = 8 groups of 128; each group handles 4 rows/iter.
    {
        const int sub = tid >> 7;              // 0..7: group id
        const int j   = tid & 127;             // float4 index within row

        for (int base = bid * 32 + sub * 4; base < ROWS_; base += GRID_ * 32) {
            int p[4];
#pragma unroll
            for (int k = 0; k < 4; k++)
                p[k] = g_pos[base + k];

            float4 v4[4];
#pragma unroll
            for (int k = 0; k < 4; k++) {
                if (p[k] >= 0)
                    v4[k] = reinterpret_cast<const float4*>(feat + (size_t)(base + k) * F_)[j];
            }
#pragma unroll
            for (int k = 0; k < 4; k++) {
                if (p[k] >= 0) {
                    const int b = (base + k) >> 12;          // T_ = 4096
                    float4* d = reinterpret_cast<float4*>(out + ((size_t)b * T_ + p[k]) * F_);
                    __stcs(&d[j], v4[k]);
                }
            }
        }
    }
}

extern "C" void kernel_launch(void* const* d_in, const int* in_sizes, int n_in,
                              void* d_out, int out_size) {
    const float* feat = (const float*)d_in[0];
    const float* W    = (const float*)d_in[1];
    float* out        = (float*)d_out;
    k_fused<<<GRID_, BLK_>>>(feat, W, out, out_size);
}